// round 7
// baseline (speedup 1.0000x reference)
#include <cuda_runtime.h>

#define ETA_MIN 0.6931471805599453f
#define ETA_MAX 10.0f

// out[i] = loss[i] > eta ? 0 : 1 - loss[i]/eta,  eta = clamp(eta_value[0], ln2, 10)
// Champion structure (R3/R6): 4 independent front-batched LDG.128 per thread,
// flat block-tiled grid, 512 threads, default stores.
// Single change this round: __ldlu (last-use) loads — input is never re-read,
// so free its L2 lines on delivery to give the write stream more L2 room.

__device__ __forceinline__ float4 weight4(float4 a, float eta, float inv_eta) {
    float4 r;
    r.x = (a.x > eta) ? 0.0f : fmaf(-a.x, inv_eta, 1.0f);
    r.y = (a.y > eta) ? 0.0f : fmaf(-a.y, inv_eta, 1.0f);
    r.z = (a.z > eta) ? 0.0f : fmaf(-a.z, inv_eta, 1.0f);
    r.w = (a.w > eta) ? 0.0f : fmaf(-a.w, inv_eta, 1.0f);
    return r;
}

__global__ __launch_bounds__(512) void weights_kernel(
    const float4* __restrict__ loss4,
    const float* __restrict__ eta_value,
    float4* __restrict__ out4,
    int n4)
{
    float eta = eta_value[0];
    eta = fminf(fmaxf(eta, ETA_MIN), ETA_MAX);
    float inv_eta = 1.0f / eta;

    const int T = 512;
    int base = blockIdx.x * (T * 4) + threadIdx.x;

    if (base + 3 * T < n4) {
        // Hot path: 4 independent last-use LDG.128 front-batched.
        float4 a0 = __ldlu(&loss4[base]);
        float4 a1 = __ldlu(&loss4[base + T]);
        float4 a2 = __ldlu(&loss4[base + 2 * T]);
        float4 a3 = __ldlu(&loss4[base + 3 * T]);

        out4[base]         = weight4(a0, eta, inv_eta);
        out4[base + T]     = weight4(a1, eta, inv_eta);
        out4[base + 2 * T] = weight4(a2, eta, inv_eta);
        out4[base + 3 * T] = weight4(a3, eta, inv_eta);
    } else {
        #pragma unroll
        for (int k = 0; k < 4; k++) {
            int idx = base + k * T;
            if (idx < n4) {
                float4 a = __ldlu(&loss4[idx]);
                out4[idx] = weight4(a, eta, inv_eta);
            }
        }
    }
}

// Scalar tail for n % 4 != 0 (not hit for N=2^25; kept for generality).
__global__ void weights_tail_kernel(
    const float* __restrict__ loss,
    const float* __restrict__ eta_value,
    float* __restrict__ out,
    int start, int n)
{
    int i = start + blockIdx.x * blockDim.x + threadIdx.x;
    if (i < n) {
        float eta = eta_value[0];
        eta = fminf(fmaxf(eta, ETA_MIN), ETA_MAX);
        float v = loss[i];
        out[i] = (v > eta) ? 0.0f : 1.0f - v / eta;
    }
}

extern "C" void kernel_launch(void* const* d_in, const int* in_sizes, int n_in,
                              void* d_out, int out_size)
{
    const float* loss = (const float*)d_in[0];
    const float* eta_value = (const float*)d_in[1];
    float* out = (float*)d_out;
    int n = in_sizes[0];

    int n4 = n / 4;
    int vec_elems = n4 * 4;

    const int threads = 512;
    const int per_block = threads * 4;  // 2048 float4 per block
    int blocks = (n4 + per_block - 1) / per_block;  // 4096 for N=2^25

    if (blocks > 0) {
        weights_kernel<<<blocks, threads>>>(
            (const float4*)loss, eta_value, (float4*)out, n4);
    }
    int tail = n - vec_elems;
    if (tail > 0) {
        int tb = (tail + 255) / 256;
        weights_tail_kernel<<<tb, 256>>>(loss, eta_value, out, vec_elems, n);
    }
}